// round 16
// baseline (speedup 1.0000x reference)
#include <cuda_runtime.h>
#include <cuda_bf16.h>
#include <cstdint>

// ---------------------------------------------------------------------------
// RegionModel round-16: R15 + zero-padded halo activation layouts.
// All activation buffers carry a 1-px zero border (device globals are
// zero-initialized; epilogues write only the interior), so every im2col /
// tile cp.async is unconditionally valid -> no bounds checks or predicates
// in staging. Layouts:
//   image planes: [B][258][260][4]  (y+1, x+1)
//   b1 planes:    [B][130][130][32]
//   b2 planes:    [B][66][66][64]
// conv1 direct-from-tile, conv2/conv3 im2col pipeline (2 CTAs/SM), conv3
// N-split + fused GAP. Split-bf16 3-term fp32 emulation (Ah*Bh+Ah*Bl+Al*Bh).
// ---------------------------------------------------------------------------

#define B_ 128
#define R_ 8

typedef unsigned int u32;
typedef unsigned long long u64;
typedef unsigned short u16;

// Padded activation planes (zero-init; borders never written)
__device__ __align__(16) __nv_bfloat16 g_imgh[(size_t)B_ * 258 * 260 * 4];
__device__ __align__(16) __nv_bfloat16 g_imgl[(size_t)B_ * 258 * 260 * 4];
__device__ __align__(16) __nv_bfloat16 g_b1h[(size_t)B_ * 130 * 130 * 32];
__device__ __align__(16) __nv_bfloat16 g_b1l[(size_t)B_ * 130 * 130 * 32];
__device__ __align__(16) __nv_bfloat16 g_b2h[(size_t)B_ * 66 * 66 * 64];
__device__ __align__(16) __nv_bfloat16 g_b2l[(size_t)B_ * 66 * 66 * 64];
__device__ float g_part[B_ * 8 * 128];
// Weight images: w1: [R][hi|lo][32][72] (k=ty*16+tx*4+ci, KP=48)
//                w2/w3: [R][NC][hi|lo][NTOT][72] (k=tap*CINP+ci)
__device__ __align__(16) __nv_bfloat16 g_w1img[R_ * 2 * 32 * 72];
__device__ __align__(16) __nv_bfloat16 g_w2img[R_ * 5 * 2 * 64 * 72];
__device__ __align__(16) __nv_bfloat16 g_w3img[R_ * 9 * 2 * 128 * 72];

__device__ __forceinline__ u32 smem_u32(const void* p) {
    u32 a;
    asm("{ .reg .u64 t; cvta.to.shared.u64 t, %1; cvt.u32.u64 %0, t; }"
        : "=r"(a) : "l"(p));
    return a;
}
#define CP16(dst, src) \
    asm volatile("cp.async.cg.shared.global [%0], [%1], 16;" :: "r"(dst), "l"(src))
#define CP8(dst, src) \
    asm volatile("cp.async.ca.shared.global [%0], [%1], 8;" :: "r"(dst), "l"(src))
#define CP_COMMIT() asm volatile("cp.async.commit_group;" ::: "memory")
#define CP_WAIT0()  asm volatile("cp.async.wait_group 0;" ::: "memory")
#define CP_WAIT1()  asm volatile("cp.async.wait_group 1;" ::: "memory")
#define LDSM4(r, a) \
    asm volatile("ldmatrix.sync.aligned.m8n8.x4.shared.b16 {%0,%1,%2,%3}, [%4];" \
                 : "=r"((r)[0]), "=r"((r)[1]), "=r"((r)[2]), "=r"((r)[3]) : "r"(a))
#define MMA(acc, af, b0, b1) \
    asm volatile( \
        "mma.sync.aligned.m16n8k16.row.col.f32.bf16.bf16.f32 " \
        "{%0,%1,%2,%3}, {%4,%5,%6,%7}, {%8,%9}, {%0,%1,%2,%3};" \
        : "+f"((acc)[0]), "+f"((acc)[1]), "+f"((acc)[2]), "+f"((acc)[3]) \
        : "r"((af)[0]), "r"((af)[1]), "r"((af)[2]), "r"((af)[3]), "r"(b0), "r"(b1))

// ---------------------------------------------------------------------------
// Fused prep: image split (into padded layout) + all 3 weight images.
// ---------------------------------------------------------------------------
#define NB_IMG 32768
#define NB_W1  144
#define NB_W2  1800
#define NB_W3  5184

__device__ __forceinline__ void prep_w_body(
    const float* __restrict__ W, __nv_bfloat16* __restrict__ img,
    int idx, int CIN, int CINP, int COUT, int NC)
{
    const int KP = 9 * CINP;
    if (idx >= R_ * NC * 2 * COUT * 72) return;
    const int kl = idx % 72;
    int t = idx / 72;
    const int n  = t % COUT; t /= COUT;
    const int hl = t % 2;    t /= 2;
    const int c  = t % NC;
    const int r  = t / NC;
    __nv_bfloat16 ob = __float2bfloat16_rn(0.0f);
    const int k = c * 64 + kl;
    if (kl < 64 && k < KP) {
        const int tap = k / CINP, ci = k % CINP;
        if (tap < 9 && ci < CIN) {
            const float w = W[(((size_t)r * COUT + n) * CIN + ci) * 9 + tap];
            const __nv_bfloat16 h = __float2bfloat16_rn(w);
            ob = hl ? __float2bfloat16_rn(w - __bfloat162float(h)) : h;
        }
    }
    img[idx] = ob;
}

__global__ void __launch_bounds__(256) prep_all(
    const float* __restrict__ img,
    __nv_bfloat16* __restrict__ oh, __nv_bfloat16* __restrict__ ol,
    const float* __restrict__ w1, __nv_bfloat16* __restrict__ w1img,
    const float* __restrict__ w2, __nv_bfloat16* __restrict__ w2img,
    const float* __restrict__ w3, __nv_bfloat16* __restrict__ w3img)
{
    const int bx = blockIdx.x;
    if (bx < NB_IMG) {
        const int idx = bx * 256 + threadIdx.x;
        const int b = idx >> 16, p = idx & 65535;
        const int y = p >> 8, x = p & 255;
        const float* ip = img + (size_t)b * 3 * 65536 + p;
        u16 h[4], l[4];
#pragma unroll
        for (int c = 0; c < 3; c++) {
            const float xv = __ldg(ip + (size_t)c * 65536);
            const __nv_bfloat16 hb = __float2bfloat16_rn(xv);
            h[c] = __bfloat16_as_ushort(hb);
            l[c] = __bfloat16_as_ushort(__float2bfloat16_rn(xv - __bfloat162float(hb)));
        }
        h[3] = 0; l[3] = 0;
        const size_t d = ((size_t)b * 258 + y + 1) * 260 + x + 1;   // u64 index
        ((u64*)oh)[d] = *(const u64*)h;
        ((u64*)ol)[d] = *(const u64*)l;
    } else if (bx < NB_IMG + NB_W1) {
        // conv1: k = ty*16 + tx*4 + ci (tx=3 / ci=3 pads -> 0), KP=48
        const int idx = (bx - NB_IMG) * 256 + threadIdx.x;
        if (idx >= R_ * 2 * 32 * 72) return;
        const int kl = idx % 72;
        int t = idx / 72;
        const int n  = t % 32; t /= 32;
        const int hl = t % 2;
        const int r  = t / 2;
        __nv_bfloat16 ob = __float2bfloat16_rn(0.0f);
        if (kl < 48) {
            const int ty = kl >> 4, rem = kl & 15, tx = rem >> 2, ci = rem & 3;
            if (tx < 3 && ci < 3) {
                const float w = w1[(((size_t)r * 32 + n) * 3 + ci) * 9 + ty * 3 + tx];
                const __nv_bfloat16 h = __float2bfloat16_rn(w);
                ob = hl ? __float2bfloat16_rn(w - __bfloat162float(h)) : h;
            }
        }
        w1img[idx] = ob;
    } else if (bx < NB_IMG + NB_W1 + NB_W2) {
        prep_w_body(w2, w2img, (bx - NB_IMG - NB_W1) * 256 + threadIdx.x,
                    32, 32, 64, 5);
    } else {
        prep_w_body(w3, w3img, (bx - NB_IMG - NB_W1 - NB_W2) * 256 + threadIdx.x,
                    64, 64, 128, 9);
    }
}

// ---------------------------------------------------------------------------
// conv1: direct-from-tile on padded image (no bounds checks).
// grid = (32, 1, B). 256 threads, WM=8 x WN=1. Tile: 9 rows x 260 px x 4ch.
// Output: b1 padded [130][130][32].
// ---------------------------------------------------------------------------
__global__ void __launch_bounds__(256) conv1_k(
    const __nv_bfloat16* __restrict__ src_h, const __nv_bfloat16* __restrict__ src_l,
    const __nv_bfloat16* __restrict__ wimg, const float* __restrict__ Bias,
    const int* __restrict__ region,
    __nv_bfloat16* __restrict__ out_h, __nv_bfloat16* __restrict__ out_l)
{
    constexpr int ROWW = 260;
    constexpr int APLANE = 9 * ROWW * 4 * 2;     // 18720 B per plane
    constexpr int MF = 4, NF = 4;

    extern __shared__ __align__(16) char sm[];
    const u32 Au = smem_u32(sm);
    const u32 Bhi = Au + 2 * APLANE;
    const u32 Blo = Bhi + 32 * 144;

    const int tid = threadIdx.x, lane = tid & 31, wid = tid >> 5;
    const int b   = blockIdx.z;
    const int r   = region[b] & (R_ - 1);
    const int oy0 = blockIdx.x * 4;
    const int g   = lane >> 2, tc = lane & 3;
    const int M0  = wid * 64;
    const int khalf = lane >> 4;
    const int mrow16 = (lane & 7) + ((lane >> 3) & 1) * 8;

    int rowb[MF], jb[MF];
#pragma unroll
    for (int mf = 0; mf < MF; mf++) {
        const int m = M0 + mf * 16 + mrow16;
        rowb[mf] = 2 * (m >> 7);
        jb[mf]   = 2 * (m & 127);
    }
    const int bl_off = ((lane & 7) + ((lane >> 4) & 1) * 8) * 144
                     + ((lane >> 3) & 1) * 16;

    float acc[MF][NF][4];
#pragma unroll
    for (int mf = 0; mf < MF; mf++)
#pragma unroll
        for (int nf = 0; nf < NF; nf++)
            acc[mf][nf][0] = acc[mf][nf][1] = acc[mf][nf][2] = acc[mf][nf][3] = 0.f;

    // ---- stage input tile (both planes, unconditional) + B once ----
    {
        constexpr int UA8 = 9 * ROWW;
        const size_t row0 = (size_t)b * 258 + 8 * blockIdx.x;   // padded row
        for (int i = tid; i < 2 * UA8; i += 256) {
            const int pl = (i >= UA8);
            const int u  = i - pl * UA8;
            const int rr = u / ROWW, t = u - rr * ROWW;
            const size_t off = ((row0 + rr) * 260 + t) * 4;
            const u32 d = Au + pl * APLANE + (rr * ROWW + t) * 8;
            CP8(d, (pl ? src_l : src_h) + off);
        }
        const char* ws = (const char*)(wimg + (size_t)r * 2 * 32 * 72);
        for (int i = tid; i < 2 * 32 * 9; i += 256)
            CP16(Bhi + i * 16, ws + (size_t)i * 16);
    }
    CP_COMMIT();
    CP_WAIT0();
    __syncthreads();

    // ---- MMA: 3 k-steps (ty), 3 terms ----
#pragma unroll
    for (int ks = 0; ks < 3; ks++) {
        const int kb = ks * 32;
        u32 aaddr[MF];
#pragma unroll
        for (int mf = 0; mf < MF; mf++)
            aaddr[mf] = Au + (((rowb[mf] + ks) * ROWW + jb[mf] + khalf * 2) << 3);

        u32 bfh[NF / 2][4], bfl[NF / 2][4];
#pragma unroll
        for (int np = 0; np < NF / 2; np++) {
            LDSM4(bfh[np], Bhi + (np * 16) * 144 + kb + bl_off);
            LDSM4(bfl[np], Blo + (np * 16) * 144 + kb + bl_off);
        }
        u32 af[MF][4];
#pragma unroll
        for (int mf = 0; mf < MF; mf++) LDSM4(af[mf], aaddr[mf]);
#pragma unroll
        for (int mf = 0; mf < MF; mf++)
#pragma unroll
            for (int nf = 0; nf < NF; nf++) {
                const u32 b0h = bfh[nf >> 1][(nf & 1) ? 2 : 0];
                const u32 b1h = bfh[nf >> 1][(nf & 1) ? 3 : 1];
                const u32 b0l = bfl[nf >> 1][(nf & 1) ? 2 : 0];
                const u32 b1l = bfl[nf >> 1][(nf & 1) ? 3 : 1];
                MMA(acc[mf][nf], af[mf], b0h, b1h);
                MMA(acc[mf][nf], af[mf], b0l, b1l);
            }
#pragma unroll
        for (int mf = 0; mf < MF; mf++) LDSM4(af[mf], aaddr[mf] + APLANE);
#pragma unroll
        for (int mf = 0; mf < MF; mf++)
#pragma unroll
            for (int nf = 0; nf < NF; nf++) {
                const u32 b0h = bfh[nf >> 1][(nf & 1) ? 2 : 0];
                const u32 b1h = bfh[nf >> 1][(nf & 1) ? 3 : 1];
                MMA(acc[mf][nf], af[mf], b0h, b1h);
            }
    }

    // ---- epilogue: bias + ReLU -> padded b1 ----
    const float* bias_g = Bias + r * 32;
#pragma unroll
    for (int mf = 0; mf < MF; mf++)
#pragma unroll
        for (int half = 0; half < 2; half++) {
            const int m  = M0 + mf * 16 + g + half * 8;
            const int oy = oy0 + (m >> 7), ox = m & 127;
            const size_t base = (((size_t)b * 130 + oy + 1) * 130 + ox + 1) * 32;
#pragma unroll
            for (int nf = 0; nf < NF; nf++) {
                const int n = nf * 8 + tc * 2;
                const float y0 = fmaxf(acc[mf][nf][half * 2 + 0] + __ldg(bias_g + n), 0.f);
                const float y1 = fmaxf(acc[mf][nf][half * 2 + 1] + __ldg(bias_g + n + 1), 0.f);
                const __nv_bfloat16 h0 = __float2bfloat16_rn(y0);
                const __nv_bfloat16 h1 = __float2bfloat16_rn(y1);
                const __nv_bfloat16 l0 = __float2bfloat16_rn(y0 - __bfloat162float(h0));
                const __nv_bfloat16 l1 = __float2bfloat16_rn(y1 - __bfloat162float(h1));
                *(u32*)(out_h + base + n) =
                    (u32)__bfloat16_as_ushort(h0) | ((u32)__bfloat16_as_ushort(h1) << 16);
                *(u32*)(out_l + base + n) =
                    (u32)__bfloat16_as_ushort(l0) | ((u32)__bfloat16_as_ushort(l1) << 16);
            }
        }
}

// ---------------------------------------------------------------------------
// conv2/conv3: im2col implicit GEMM on padded inputs (no bounds checks).
// HP = padded input pitch (HIN+2). Padded output pitch = HOUT+2 (when !GAP).
// ---------------------------------------------------------------------------
template <int CINP, int LOGC, int COUT, int NTOT, int HOUT, int LOGH,
          int WM, int WN, bool GAP>
__global__ void __launch_bounds__(256) conv_mma8(
    const __nv_bfloat16* __restrict__ src_h, const __nv_bfloat16* __restrict__ src_l,
    const __nv_bfloat16* __restrict__ wimg, const float* __restrict__ Bias,
    const int* __restrict__ region, float* __restrict__ part,
    __nv_bfloat16* __restrict__ out_h, __nv_bfloat16* __restrict__ out_l)
{
    constexpr int HP   = 2 * HOUT + 2;          // padded input pitch
    constexpr int OP   = HOUT + 2;              // padded output pitch
    constexpr int KP   = 9 * CINP;
    constexpr int NC   = (KP + 63) / 64;
    constexpr int MF   = 128 / (16 * WM);
    constexpr int NF   = COUT / (8 * WN);
    constexpr int SSB  = 2 * 18432 + 2 * COUT * 144;

    extern __shared__ __align__(16) char sm[];

    const int tid = threadIdx.x, lane = tid & 31, wid = tid >> 5;
    const int b   = blockIdx.z;
    const int px0 = blockIdx.x * 128;
    const int n0  = blockIdx.y * COUT;
    const int r   = region[b] & (R_ - 1);
    const int g   = lane >> 2, tc = lane & 3;
    const int wm  = wid & (WM - 1), wn = wid / WM;
    const int M0  = wm * (128 / WM);
    const int N0  = wn * (COUT / WN);

    const int al_off = ((lane & 7) + ((lane >> 3) & 1) * 8) * 144 + (lane >> 4) * 16;
    const int bl_off = ((lane & 7) + ((lane >> 4) & 1) * 8) * 144
                     + ((lane >> 3) & 1) * 16;

    float acc[MF][NF][4];
#pragma unroll
    for (int mf = 0; mf < MF; mf++)
#pragma unroll
        for (int nf = 0; nf < NF; nf++)
            acc[mf][nf][0] = acc[mf][nf][1] = acc[mf][nf][2] = acc[mf][nf][3] = 0.f;

    const __nv_bfloat16* wr = wimg + (size_t)r * NC * 2 * NTOT * 72;

    auto stage = [&](int c, int s) {
        char* sb = sm + s * SSB;
        const u32 au = smem_u32(sb);
        const u32 bu = au + 2 * 18432;
        const u16* src = (const u16*)wr + (size_t)c * 2 * NTOT * 72;
        for (int i = tid; i < 2 * COUT * 9; i += 256) {
            const int half = i / (COUT * 9);
            const int rem  = i - half * COUT * 9;
            const int row  = rem / 9, u = rem - row * 9;
            const u16* sp = src + (size_t)half * NTOT * 72 + (n0 + row) * 72 + u * 8;
            CP16(bu + half * COUT * 144 + row * 144 + u * 16, sp);
        }
        for (int i = tid; i < 1024; i += 256) {
            const int m = i >> 3, q = i & 7;
            const int k = c * 64 + q * 8;
            if (k >= KP) continue;                     // conv2 last chunk only
            const int tap = k >> LOGC, ci0 = k & (CINP - 1);
            const int ty = tap / 3, tx2 = tap - 3 * ty;
            const int px = px0 + m;
            const int oy = px >> LOGH, ox = px & (HOUT - 1);
            const size_t off =
                (((size_t)b * HP + 2 * oy + ty) * HP + 2 * ox + tx2) * CINP + ci0;
            const u32 d = au + m * 144 + q * 16;
            CP16(d, src_h + off);
            CP16(d + 18432, src_l + off);
        }
        CP_COMMIT();
    };

    auto domma = [&](int c, int s) {
        const int rem = KP - c * 64;
        const int nks = (rem >= 64) ? 4 : ((rem + 15) >> 4);
        const u32 au  = smem_u32(sm + s * SSB);
        const u32 Ahi = au, Alo = au + 18432;
        const u32 Bhi = au + 2 * 18432, Blo = Bhi + COUT * 144;
#pragma unroll 4
        for (int ks = 0; ks < nks; ks++) {
            const int kb = ks * 32;
            u32 bfh[NF / 2][4], bfl[NF / 2][4];
#pragma unroll
            for (int np = 0; np < NF / 2; np++) {
                LDSM4(bfh[np], Bhi + (N0 + np * 16) * 144 + kb + bl_off);
                LDSM4(bfl[np], Blo + (N0 + np * 16) * 144 + kb + bl_off);
            }
            u32 af[MF][4];
#pragma unroll
            for (int mf = 0; mf < MF; mf++)
                LDSM4(af[mf], Ahi + (M0 + mf * 16) * 144 + kb + al_off);
#pragma unroll
            for (int mf = 0; mf < MF; mf++)
#pragma unroll
                for (int nf = 0; nf < NF; nf++) {
                    const u32 b0h = bfh[nf >> 1][(nf & 1) ? 2 : 0];
                    const u32 b1h = bfh[nf >> 1][(nf & 1) ? 3 : 1];
                    const u32 b0l = bfl[nf >> 1][(nf & 1) ? 2 : 0];
                    const u32 b1l = bfl[nf >> 1][(nf & 1) ? 3 : 1];
                    MMA(acc[mf][nf], af[mf], b0h, b1h);
                    MMA(acc[mf][nf], af[mf], b0l, b1l);
                }
#pragma unroll
            for (int mf = 0; mf < MF; mf++)
                LDSM4(af[mf], Alo + (M0 + mf * 16) * 144 + kb + al_off);
#pragma unroll
            for (int mf = 0; mf < MF; mf++)
#pragma unroll
                for (int nf = 0; nf < NF; nf++) {
                    const u32 b0h = bfh[nf >> 1][(nf & 1) ? 2 : 0];
                    const u32 b1h = bfh[nf >> 1][(nf & 1) ? 3 : 1];
                    MMA(acc[mf][nf], af[mf], b0h, b1h);
                }
        }
    };

    stage(0, 0);
    if (NC > 1) stage(1, 1);
    for (int c = 0; c < NC; c++) {
        if (c + 1 < NC) { CP_WAIT1(); } else { CP_WAIT0(); }
        __syncthreads();
        domma(c, c & 1);
        __syncthreads();
        if (c + 2 < NC) stage(c + 2, c & 1);
    }

    const float* bias_g = Bias + r * NTOT + n0;
    if (GAP) {
        float s0[NF], s1[NF];
#pragma unroll
        for (int nf = 0; nf < NF; nf++) { s0[nf] = 0.f; s1[nf] = 0.f; }
#pragma unroll
        for (int mf = 0; mf < MF; mf++)
#pragma unroll
            for (int half = 0; half < 2; half++)
#pragma unroll
                for (int nf = 0; nf < NF; nf++) {
                    const int n = N0 + nf * 8 + tc * 2;
                    s0[nf] += fmaxf(acc[mf][nf][half * 2 + 0] + __ldg(bias_g + n), 0.f);
                    s1[nf] += fmaxf(acc[mf][nf][half * 2 + 1] + __ldg(bias_g + n + 1), 0.f);
                }
#pragma unroll
        for (int o = 16; o >= 4; o >>= 1)
#pragma unroll
            for (int nf = 0; nf < NF; nf++) {
                s0[nf] += __shfl_down_sync(0xFFFFFFFFu, s0[nf], o);
                s1[nf] += __shfl_down_sync(0xFFFFFFFFu, s1[nf], o);
            }
        __syncthreads();
        float* red = (float*)sm;
        if (lane < 4)
#pragma unroll
            for (int nf = 0; nf < NF; nf++) {
                red[(wid * NF + nf) * 8 + tc * 2 + 0] = s0[nf];
                red[(wid * NF + nf) * 8 + tc * 2 + 1] = s1[nf];
            }
        __syncthreads();
        if (tid < WN * NF * 8) {
            const int wn2 = tid / (NF * 8);
            const int rem = tid - wn2 * NF * 8;
            const int nf = rem >> 3, j = rem & 7;
            float t = 0.f;
#pragma unroll
            for (int w2 = 0; w2 < WM; w2++)
                t += red[((wn2 * WM + w2) * NF + nf) * 8 + j];
            const int n = n0 + wn2 * (COUT / WN) + nf * 8 + j;
            part[((size_t)b * 8 + blockIdx.x) * 128 + n] = t;
        }
    } else {
#pragma unroll
        for (int mf = 0; mf < MF; mf++)
#pragma unroll
            for (int half = 0; half < 2; half++) {
                const int m  = M0 + mf * 16 + g + half * 8;
                const int px = px0 + m;
                const int oy = px >> LOGH, ox = px & (HOUT - 1);
                const size_t base =
                    (((size_t)b * OP + oy + 1) * OP + ox + 1) * NTOT + n0;
#pragma unroll
                for (int nf = 0; nf < NF; nf++) {
                    const int n = N0 + nf * 8 + tc * 2;
                    const float y0 = fmaxf(acc[mf][nf][half * 2 + 0] + __ldg(bias_g + n), 0.f);
                    const float y1 = fmaxf(acc[mf][nf][half * 2 + 1] + __ldg(bias_g + n + 1), 0.f);
                    const __nv_bfloat16 h0 = __float2bfloat16_rn(y0);
                    const __nv_bfloat16 h1 = __float2bfloat16_rn(y1);
                    const __nv_bfloat16 l0 = __float2bfloat16_rn(y0 - __bfloat162float(h0));
                    const __nv_bfloat16 l1 = __float2bfloat16_rn(y1 - __bfloat162float(h1));
                    *(u32*)(out_h + base + n) =
                        (u32)__bfloat16_as_ushort(h0) | ((u32)__bfloat16_as_ushort(h1) << 16);
                    *(u32*)(out_l + base + n) =
                        (u32)__bfloat16_as_ushort(l0) | ((u32)__bfloat16_as_ushort(l1) << 16);
                }
            }
    }
}

// ---------------------------------------------------------------------------
__global__ void __launch_bounds__(128) fc_k(const float* __restrict__ part,
                                            const float* __restrict__ fw,
                                            const float* __restrict__ fb,
                                            const int* __restrict__ region,
                                            float* __restrict__ out)
{
    __shared__ float f[128];
    const int b = blockIdx.x, tid = threadIdx.x;
    const int r = region[b] & (R_ - 1);
    float s = 0.0f;
#pragma unroll
    for (int q = 0; q < 8; q++) s += part[(b * 8 + q) * 128 + tid];
    f[tid] = s * (1.0f / 1024.0f);
    __syncthreads();
    if (tid < 32) {
        const float* w0 = fw + ((size_t)r * 2 + 0) * 128;
        const float* w1 = fw + ((size_t)r * 2 + 1) * 128;
        float p0 = 0.0f, p1 = 0.0f;
#pragma unroll
        for (int i = tid; i < 128; i += 32) {
            p0 = fmaf(f[i], w0[i], p0);
            p1 = fmaf(f[i], w1[i], p1);
        }
#pragma unroll
        for (int o = 16; o > 0; o >>= 1) {
            p0 += __shfl_down_sync(0xFFFFFFFFu, p0, o);
            p1 += __shfl_down_sync(0xFFFFFFFFu, p1, o);
        }
        if (tid == 0) {
            out[b * 2 + 0] = p0 + fb[r * 2 + 0];
            out[b * 2 + 1] = p1 + fb[r * 2 + 1];
        }
    }
}

// ---------------------------------------------------------------------------
extern "C" void kernel_launch(void* const* d_in, const int* in_sizes, int n_in,
                              void* d_out, int out_size)
{
    const float* image  = (const float*)d_in[0];
    const int*   region = (const int*)d_in[1];
    const float* w1     = (const float*)d_in[2];
    const float* b1     = (const float*)d_in[3];
    const float* w2     = (const float*)d_in[4];
    const float* b2     = (const float*)d_in[5];
    const float* w3     = (const float*)d_in[6];
    const float* b3     = (const float*)d_in[7];
    const float* fw     = (const float*)d_in[8];
    const float* fb     = (const float*)d_in[9];
    float* out = (float*)d_out;

    __nv_bfloat16 *imgh, *imgl, *b1h, *b1l, *b2h, *b2l, *w1img, *w2img, *w3img;
    float *part;
    cudaGetSymbolAddress((void**)&imgh, g_imgh);
    cudaGetSymbolAddress((void**)&imgl, g_imgl);
    cudaGetSymbolAddress((void**)&b1h, g_b1h);
    cudaGetSymbolAddress((void**)&b1l, g_b1l);
    cudaGetSymbolAddress((void**)&b2h, g_b2h);
    cudaGetSymbolAddress((void**)&b2l, g_b2l);
    cudaGetSymbolAddress((void**)&part, g_part);
    cudaGetSymbolAddress((void**)&w1img, g_w1img);
    cudaGetSymbolAddress((void**)&w2img, g_w2img);
    cudaGetSymbolAddress((void**)&w3img, g_w3img);

    prep_all<<<NB_IMG + NB_W1 + NB_W2 + NB_W3, 256>>>(
        image, imgh, imgl, w1, w1img, w2, w2img, w3, w3img);

    const int SM1 = 2 * 18720 + 2 * 32 * 144;     //  46656
    const int SM2 = 2 * (36864 + 2 * 64 * 144);   // 110592 -> 2 CTAs/SM
    const int SM3 = SM2;
    cudaFuncSetAttribute(conv1_k,
                         cudaFuncAttributeMaxDynamicSharedMemorySize, SM1);
    cudaFuncSetAttribute(conv_mma8<32, 5, 64, 64, 64, 6, 4, 2, false>,
                         cudaFuncAttributeMaxDynamicSharedMemorySize, SM2);
    cudaFuncSetAttribute(conv_mma8<64, 6, 64, 128, 32, 5, 4, 2, true>,
                         cudaFuncAttributeMaxDynamicSharedMemorySize, SM3);

    // conv1: direct-from-tile on padded image
    conv1_k<<<dim3(32, 1, B_), 256, SM1>>>(
        imgh, imgl, w1img, b1, region, b1h, b1l);
    // conv2: padded in/out
    conv_mma8<32, 5, 64, 64, 64, 6, 4, 2, false><<<dim3(32, 1, B_), 256, SM2>>>(
        b1h, b1l, w2img, b2, region, nullptr, b2h, b2l);
    // conv3: padded in, N-split + fused GAP
    conv_mma8<64, 6, 64, 128, 32, 5, 4, 2, true><<<dim3(8, 2, B_), 256, SM3>>>(
        b2h, b2l, w3img, b3, region, part, nullptr, nullptr);

    fc_k<<<B_, 128>>>(part, fw, fb, region, out);
}

// round 17
// speedup vs baseline: 1.0015x; 1.0015x over previous
#include <cuda_runtime.h>
#include <cuda_bf16.h>
#include <cstdint>

// ---------------------------------------------------------------------------
// RegionModel round-16: R15 + zero-padded halo activation layouts.
// All activation buffers carry a 1-px zero border (device globals are
// zero-initialized; epilogues write only the interior), so every im2col /
// tile cp.async is unconditionally valid -> no bounds checks or predicates
// in staging. Layouts:
//   image planes: [B][258][260][4]  (y+1, x+1)
//   b1 planes:    [B][130][130][32]
//   b2 planes:    [B][66][66][64]
// conv1 direct-from-tile, conv2/conv3 im2col pipeline (2 CTAs/SM), conv3
// N-split + fused GAP. Split-bf16 3-term fp32 emulation (Ah*Bh+Ah*Bl+Al*Bh).
// ---------------------------------------------------------------------------

#define B_ 128
#define R_ 8

typedef unsigned int u32;
typedef unsigned long long u64;
typedef unsigned short u16;

// Padded activation planes (zero-init; borders never written)
__device__ __align__(16) __nv_bfloat16 g_imgh[(size_t)B_ * 258 * 260 * 4];
__device__ __align__(16) __nv_bfloat16 g_imgl[(size_t)B_ * 258 * 260 * 4];
__device__ __align__(16) __nv_bfloat16 g_b1h[(size_t)B_ * 130 * 130 * 32];
__device__ __align__(16) __nv_bfloat16 g_b1l[(size_t)B_ * 130 * 130 * 32];
__device__ __align__(16) __nv_bfloat16 g_b2h[(size_t)B_ * 66 * 66 * 64];
__device__ __align__(16) __nv_bfloat16 g_b2l[(size_t)B_ * 66 * 66 * 64];
__device__ float g_part[B_ * 8 * 128];
// Weight images: w1: [R][hi|lo][32][72] (k=ty*16+tx*4+ci, KP=48)
//                w2/w3: [R][NC][hi|lo][NTOT][72] (k=tap*CINP+ci)
__device__ __align__(16) __nv_bfloat16 g_w1img[R_ * 2 * 32 * 72];
__device__ __align__(16) __nv_bfloat16 g_w2img[R_ * 5 * 2 * 64 * 72];
__device__ __align__(16) __nv_bfloat16 g_w3img[R_ * 9 * 2 * 128 * 72];

__device__ __forceinline__ u32 smem_u32(const void* p) {
    u32 a;
    asm("{ .reg .u64 t; cvta.to.shared.u64 t, %1; cvt.u32.u64 %0, t; }"
        : "=r"(a) : "l"(p));
    return a;
}
#define CP16(dst, src) \
    asm volatile("cp.async.cg.shared.global [%0], [%1], 16;" :: "r"(dst), "l"(src))
#define CP8(dst, src) \
    asm volatile("cp.async.ca.shared.global [%0], [%1], 8;" :: "r"(dst), "l"(src))
#define CP_COMMIT() asm volatile("cp.async.commit_group;" ::: "memory")
#define CP_WAIT0()  asm volatile("cp.async.wait_group 0;" ::: "memory")
#define CP_WAIT1()  asm volatile("cp.async.wait_group 1;" ::: "memory")
#define LDSM4(r, a) \
    asm volatile("ldmatrix.sync.aligned.m8n8.x4.shared.b16 {%0,%1,%2,%3}, [%4];" \
                 : "=r"((r)[0]), "=r"((r)[1]), "=r"((r)[2]), "=r"((r)[3]) : "r"(a))
#define MMA(acc, af, b0, b1) \
    asm volatile( \
        "mma.sync.aligned.m16n8k16.row.col.f32.bf16.bf16.f32 " \
        "{%0,%1,%2,%3}, {%4,%5,%6,%7}, {%8,%9}, {%0,%1,%2,%3};" \
        : "+f"((acc)[0]), "+f"((acc)[1]), "+f"((acc)[2]), "+f"((acc)[3]) \
        : "r"((af)[0]), "r"((af)[1]), "r"((af)[2]), "r"((af)[3]), "r"(b0), "r"(b1))

// ---------------------------------------------------------------------------
// Fused prep: image split (into padded layout) + all 3 weight images.
// ---------------------------------------------------------------------------
#define NB_IMG 32768
#define NB_W1  144
#define NB_W2  1800
#define NB_W3  5184

__device__ __forceinline__ void prep_w_body(
    const float* __restrict__ W, __nv_bfloat16* __restrict__ img,
    int idx, int CIN, int CINP, int COUT, int NC)
{
    const int KP = 9 * CINP;
    if (idx >= R_ * NC * 2 * COUT * 72) return;
    const int kl = idx % 72;
    int t = idx / 72;
    const int n  = t % COUT; t /= COUT;
    const int hl = t % 2;    t /= 2;
    const int c  = t % NC;
    const int r  = t / NC;
    __nv_bfloat16 ob = __float2bfloat16_rn(0.0f);
    const int k = c * 64 + kl;
    if (kl < 64 && k < KP) {
        const int tap = k / CINP, ci = k % CINP;
        if (tap < 9 && ci < CIN) {
            const float w = W[(((size_t)r * COUT + n) * CIN + ci) * 9 + tap];
            const __nv_bfloat16 h = __float2bfloat16_rn(w);
            ob = hl ? __float2bfloat16_rn(w - __bfloat162float(h)) : h;
        }
    }
    img[idx] = ob;
}

__global__ void __launch_bounds__(256) prep_all(
    const float* __restrict__ img,
    __nv_bfloat16* __restrict__ oh, __nv_bfloat16* __restrict__ ol,
    const float* __restrict__ w1, __nv_bfloat16* __restrict__ w1img,
    const float* __restrict__ w2, __nv_bfloat16* __restrict__ w2img,
    const float* __restrict__ w3, __nv_bfloat16* __restrict__ w3img)
{
    const int bx = blockIdx.x;
    if (bx < NB_IMG) {
        const int idx = bx * 256 + threadIdx.x;
        const int b = idx >> 16, p = idx & 65535;
        const int y = p >> 8, x = p & 255;
        const float* ip = img + (size_t)b * 3 * 65536 + p;
        u16 h[4], l[4];
#pragma unroll
        for (int c = 0; c < 3; c++) {
            const float xv = __ldg(ip + (size_t)c * 65536);
            const __nv_bfloat16 hb = __float2bfloat16_rn(xv);
            h[c] = __bfloat16_as_ushort(hb);
            l[c] = __bfloat16_as_ushort(__float2bfloat16_rn(xv - __bfloat162float(hb)));
        }
        h[3] = 0; l[3] = 0;
        const size_t d = ((size_t)b * 258 + y + 1) * 260 + x + 1;   // u64 index
        ((u64*)oh)[d] = *(const u64*)h;
        ((u64*)ol)[d] = *(const u64*)l;
    } else if (bx < NB_IMG + NB_W1) {
        // conv1: k = ty*16 + tx*4 + ci (tx=3 / ci=3 pads -> 0), KP=48
        const int idx = (bx - NB_IMG) * 256 + threadIdx.x;
        if (idx >= R_ * 2 * 32 * 72) return;
        const int kl = idx % 72;
        int t = idx / 72;
        const int n  = t % 32; t /= 32;
        const int hl = t % 2;
        const int r  = t / 2;
        __nv_bfloat16 ob = __float2bfloat16_rn(0.0f);
        if (kl < 48) {
            const int ty = kl >> 4, rem = kl & 15, tx = rem >> 2, ci = rem & 3;
            if (tx < 3 && ci < 3) {
                const float w = w1[(((size_t)r * 32 + n) * 3 + ci) * 9 + ty * 3 + tx];
                const __nv_bfloat16 h = __float2bfloat16_rn(w);
                ob = hl ? __float2bfloat16_rn(w - __bfloat162float(h)) : h;
            }
        }
        w1img[idx] = ob;
    } else if (bx < NB_IMG + NB_W1 + NB_W2) {
        prep_w_body(w2, w2img, (bx - NB_IMG - NB_W1) * 256 + threadIdx.x,
                    32, 32, 64, 5);
    } else {
        prep_w_body(w3, w3img, (bx - NB_IMG - NB_W1 - NB_W2) * 256 + threadIdx.x,
                    64, 64, 128, 9);
    }
}

// ---------------------------------------------------------------------------
// conv1: direct-from-tile on padded image (no bounds checks).
// grid = (32, 1, B). 256 threads, WM=8 x WN=1. Tile: 9 rows x 260 px x 4ch.
// Output: b1 padded [130][130][32].
// ---------------------------------------------------------------------------
__global__ void __launch_bounds__(256) conv1_k(
    const __nv_bfloat16* __restrict__ src_h, const __nv_bfloat16* __restrict__ src_l,
    const __nv_bfloat16* __restrict__ wimg, const float* __restrict__ Bias,
    const int* __restrict__ region,
    __nv_bfloat16* __restrict__ out_h, __nv_bfloat16* __restrict__ out_l)
{
    constexpr int ROWW = 260;
    constexpr int APLANE = 9 * ROWW * 4 * 2;     // 18720 B per plane
    constexpr int MF = 4, NF = 4;

    extern __shared__ __align__(16) char sm[];
    const u32 Au = smem_u32(sm);
    const u32 Bhi = Au + 2 * APLANE;
    const u32 Blo = Bhi + 32 * 144;

    const int tid = threadIdx.x, lane = tid & 31, wid = tid >> 5;
    const int b   = blockIdx.z;
    const int r   = region[b] & (R_ - 1);
    const int oy0 = blockIdx.x * 4;
    const int g   = lane >> 2, tc = lane & 3;
    const int M0  = wid * 64;
    const int khalf = lane >> 4;
    const int mrow16 = (lane & 7) + ((lane >> 3) & 1) * 8;

    int rowb[MF], jb[MF];
#pragma unroll
    for (int mf = 0; mf < MF; mf++) {
        const int m = M0 + mf * 16 + mrow16;
        rowb[mf] = 2 * (m >> 7);
        jb[mf]   = 2 * (m & 127);
    }
    const int bl_off = ((lane & 7) + ((lane >> 4) & 1) * 8) * 144
                     + ((lane >> 3) & 1) * 16;

    float acc[MF][NF][4];
#pragma unroll
    for (int mf = 0; mf < MF; mf++)
#pragma unroll
        for (int nf = 0; nf < NF; nf++)
            acc[mf][nf][0] = acc[mf][nf][1] = acc[mf][nf][2] = acc[mf][nf][3] = 0.f;

    // ---- stage input tile (both planes, unconditional) + B once ----
    {
        constexpr int UA8 = 9 * ROWW;
        const size_t row0 = (size_t)b * 258 + 8 * blockIdx.x;   // padded row
        for (int i = tid; i < 2 * UA8; i += 256) {
            const int pl = (i >= UA8);
            const int u  = i - pl * UA8;
            const int rr = u / ROWW, t = u - rr * ROWW;
            const size_t off = ((row0 + rr) * 260 + t) * 4;
            const u32 d = Au + pl * APLANE + (rr * ROWW + t) * 8;
            CP8(d, (pl ? src_l : src_h) + off);
        }
        const char* ws = (const char*)(wimg + (size_t)r * 2 * 32 * 72);
        for (int i = tid; i < 2 * 32 * 9; i += 256)
            CP16(Bhi + i * 16, ws + (size_t)i * 16);
    }
    CP_COMMIT();
    CP_WAIT0();
    __syncthreads();

    // ---- MMA: 3 k-steps (ty), 3 terms ----
#pragma unroll
    for (int ks = 0; ks < 3; ks++) {
        const int kb = ks * 32;
        u32 aaddr[MF];
#pragma unroll
        for (int mf = 0; mf < MF; mf++)
            aaddr[mf] = Au + (((rowb[mf] + ks) * ROWW + jb[mf] + khalf * 2) << 3);

        u32 bfh[NF / 2][4], bfl[NF / 2][4];
#pragma unroll
        for (int np = 0; np < NF / 2; np++) {
            LDSM4(bfh[np], Bhi + (np * 16) * 144 + kb + bl_off);
            LDSM4(bfl[np], Blo + (np * 16) * 144 + kb + bl_off);
        }
        u32 af[MF][4];
#pragma unroll
        for (int mf = 0; mf < MF; mf++) LDSM4(af[mf], aaddr[mf]);
#pragma unroll
        for (int mf = 0; mf < MF; mf++)
#pragma unroll
            for (int nf = 0; nf < NF; nf++) {
                const u32 b0h = bfh[nf >> 1][(nf & 1) ? 2 : 0];
                const u32 b1h = bfh[nf >> 1][(nf & 1) ? 3 : 1];
                const u32 b0l = bfl[nf >> 1][(nf & 1) ? 2 : 0];
                const u32 b1l = bfl[nf >> 1][(nf & 1) ? 3 : 1];
                MMA(acc[mf][nf], af[mf], b0h, b1h);
                MMA(acc[mf][nf], af[mf], b0l, b1l);
            }
#pragma unroll
        for (int mf = 0; mf < MF; mf++) LDSM4(af[mf], aaddr[mf] + APLANE);
#pragma unroll
        for (int mf = 0; mf < MF; mf++)
#pragma unroll
            for (int nf = 0; nf < NF; nf++) {
                const u32 b0h = bfh[nf >> 1][(nf & 1) ? 2 : 0];
                const u32 b1h = bfh[nf >> 1][(nf & 1) ? 3 : 1];
                MMA(acc[mf][nf], af[mf], b0h, b1h);
            }
    }

    // ---- epilogue: bias + ReLU -> padded b1 ----
    const float* bias_g = Bias + r * 32;
#pragma unroll
    for (int mf = 0; mf < MF; mf++)
#pragma unroll
        for (int half = 0; half < 2; half++) {
            const int m  = M0 + mf * 16 + g + half * 8;
            const int oy = oy0 + (m >> 7), ox = m & 127;
            const size_t base = (((size_t)b * 130 + oy + 1) * 130 + ox + 1) * 32;
#pragma unroll
            for (int nf = 0; nf < NF; nf++) {
                const int n = nf * 8 + tc * 2;
                const float y0 = fmaxf(acc[mf][nf][half * 2 + 0] + __ldg(bias_g + n), 0.f);
                const float y1 = fmaxf(acc[mf][nf][half * 2 + 1] + __ldg(bias_g + n + 1), 0.f);
                const __nv_bfloat16 h0 = __float2bfloat16_rn(y0);
                const __nv_bfloat16 h1 = __float2bfloat16_rn(y1);
                const __nv_bfloat16 l0 = __float2bfloat16_rn(y0 - __bfloat162float(h0));
                const __nv_bfloat16 l1 = __float2bfloat16_rn(y1 - __bfloat162float(h1));
                *(u32*)(out_h + base + n) =
                    (u32)__bfloat16_as_ushort(h0) | ((u32)__bfloat16_as_ushort(h1) << 16);
                *(u32*)(out_l + base + n) =
                    (u32)__bfloat16_as_ushort(l0) | ((u32)__bfloat16_as_ushort(l1) << 16);
            }
        }
}

// ---------------------------------------------------------------------------
// conv2/conv3: im2col implicit GEMM on padded inputs (no bounds checks).
// HP = padded input pitch (HIN+2). Padded output pitch = HOUT+2 (when !GAP).
// ---------------------------------------------------------------------------
template <int CINP, int LOGC, int COUT, int NTOT, int HOUT, int LOGH,
          int WM, int WN, bool GAP>
__global__ void __launch_bounds__(256) conv_mma8(
    const __nv_bfloat16* __restrict__ src_h, const __nv_bfloat16* __restrict__ src_l,
    const __nv_bfloat16* __restrict__ wimg, const float* __restrict__ Bias,
    const int* __restrict__ region, float* __restrict__ part,
    __nv_bfloat16* __restrict__ out_h, __nv_bfloat16* __restrict__ out_l)
{
    constexpr int HP   = 2 * HOUT + 2;          // padded input pitch
    constexpr int OP   = HOUT + 2;              // padded output pitch
    constexpr int KP   = 9 * CINP;
    constexpr int NC   = (KP + 63) / 64;
    constexpr int MF   = 128 / (16 * WM);
    constexpr int NF   = COUT / (8 * WN);
    constexpr int SSB  = 2 * 18432 + 2 * COUT * 144;

    extern __shared__ __align__(16) char sm[];

    const int tid = threadIdx.x, lane = tid & 31, wid = tid >> 5;
    const int b   = blockIdx.z;
    const int px0 = blockIdx.x * 128;
    const int n0  = blockIdx.y * COUT;
    const int r   = region[b] & (R_ - 1);
    const int g   = lane >> 2, tc = lane & 3;
    const int wm  = wid & (WM - 1), wn = wid / WM;
    const int M0  = wm * (128 / WM);
    const int N0  = wn * (COUT / WN);

    const int al_off = ((lane & 7) + ((lane >> 3) & 1) * 8) * 144 + (lane >> 4) * 16;
    const int bl_off = ((lane & 7) + ((lane >> 4) & 1) * 8) * 144
                     + ((lane >> 3) & 1) * 16;

    float acc[MF][NF][4];
#pragma unroll
    for (int mf = 0; mf < MF; mf++)
#pragma unroll
        for (int nf = 0; nf < NF; nf++)
            acc[mf][nf][0] = acc[mf][nf][1] = acc[mf][nf][2] = acc[mf][nf][3] = 0.f;

    const __nv_bfloat16* wr = wimg + (size_t)r * NC * 2 * NTOT * 72;

    auto stage = [&](int c, int s) {
        char* sb = sm + s * SSB;
        const u32 au = smem_u32(sb);
        const u32 bu = au + 2 * 18432;
        const u16* src = (const u16*)wr + (size_t)c * 2 * NTOT * 72;
        for (int i = tid; i < 2 * COUT * 9; i += 256) {
            const int half = i / (COUT * 9);
            const int rem  = i - half * COUT * 9;
            const int row  = rem / 9, u = rem - row * 9;
            const u16* sp = src + (size_t)half * NTOT * 72 + (n0 + row) * 72 + u * 8;
            CP16(bu + half * COUT * 144 + row * 144 + u * 16, sp);
        }
        for (int i = tid; i < 1024; i += 256) {
            const int m = i >> 3, q = i & 7;
            const int k = c * 64 + q * 8;
            if (k >= KP) continue;                     // conv2 last chunk only
            const int tap = k >> LOGC, ci0 = k & (CINP - 1);
            const int ty = tap / 3, tx2 = tap - 3 * ty;
            const int px = px0 + m;
            const int oy = px >> LOGH, ox = px & (HOUT - 1);
            const size_t off =
                (((size_t)b * HP + 2 * oy + ty) * HP + 2 * ox + tx2) * CINP + ci0;
            const u32 d = au + m * 144 + q * 16;
            CP16(d, src_h + off);
            CP16(d + 18432, src_l + off);
        }
        CP_COMMIT();
    };

    auto domma = [&](int c, int s) {
        const int rem = KP - c * 64;
        const int nks = (rem >= 64) ? 4 : ((rem + 15) >> 4);
        const u32 au  = smem_u32(sm + s * SSB);
        const u32 Ahi = au, Alo = au + 18432;
        const u32 Bhi = au + 2 * 18432, Blo = Bhi + COUT * 144;
#pragma unroll 4
        for (int ks = 0; ks < nks; ks++) {
            const int kb = ks * 32;
            u32 bfh[NF / 2][4], bfl[NF / 2][4];
#pragma unroll
            for (int np = 0; np < NF / 2; np++) {
                LDSM4(bfh[np], Bhi + (N0 + np * 16) * 144 + kb + bl_off);
                LDSM4(bfl[np], Blo + (N0 + np * 16) * 144 + kb + bl_off);
            }
            u32 af[MF][4];
#pragma unroll
            for (int mf = 0; mf < MF; mf++)
                LDSM4(af[mf], Ahi + (M0 + mf * 16) * 144 + kb + al_off);
#pragma unroll
            for (int mf = 0; mf < MF; mf++)
#pragma unroll
                for (int nf = 0; nf < NF; nf++) {
                    const u32 b0h = bfh[nf >> 1][(nf & 1) ? 2 : 0];
                    const u32 b1h = bfh[nf >> 1][(nf & 1) ? 3 : 1];
                    const u32 b0l = bfl[nf >> 1][(nf & 1) ? 2 : 0];
                    const u32 b1l = bfl[nf >> 1][(nf & 1) ? 3 : 1];
                    MMA(acc[mf][nf], af[mf], b0h, b1h);
                    MMA(acc[mf][nf], af[mf], b0l, b1l);
                }
#pragma unroll
            for (int mf = 0; mf < MF; mf++)
                LDSM4(af[mf], Alo + (M0 + mf * 16) * 144 + kb + al_off);
#pragma unroll
            for (int mf = 0; mf < MF; mf++)
#pragma unroll
                for (int nf = 0; nf < NF; nf++) {
                    const u32 b0h = bfh[nf >> 1][(nf & 1) ? 2 : 0];
                    const u32 b1h = bfh[nf >> 1][(nf & 1) ? 3 : 1];
                    MMA(acc[mf][nf], af[mf], b0h, b1h);
                }
        }
    };

    stage(0, 0);
    if (NC > 1) stage(1, 1);
    for (int c = 0; c < NC; c++) {
        if (c + 1 < NC) { CP_WAIT1(); } else { CP_WAIT0(); }
        __syncthreads();
        domma(c, c & 1);
        __syncthreads();
        if (c + 2 < NC) stage(c + 2, c & 1);
    }

    const float* bias_g = Bias + r * NTOT + n0;
    if (GAP) {
        float s0[NF], s1[NF];
#pragma unroll
        for (int nf = 0; nf < NF; nf++) { s0[nf] = 0.f; s1[nf] = 0.f; }
#pragma unroll
        for (int mf = 0; mf < MF; mf++)
#pragma unroll
            for (int half = 0; half < 2; half++)
#pragma unroll
                for (int nf = 0; nf < NF; nf++) {
                    const int n = N0 + nf * 8 + tc * 2;
                    s0[nf] += fmaxf(acc[mf][nf][half * 2 + 0] + __ldg(bias_g + n), 0.f);
                    s1[nf] += fmaxf(acc[mf][nf][half * 2 + 1] + __ldg(bias_g + n + 1), 0.f);
                }
#pragma unroll
        for (int o = 16; o >= 4; o >>= 1)
#pragma unroll
            for (int nf = 0; nf < NF; nf++) {
                s0[nf] += __shfl_down_sync(0xFFFFFFFFu, s0[nf], o);
                s1[nf] += __shfl_down_sync(0xFFFFFFFFu, s1[nf], o);
            }
        __syncthreads();
        float* red = (float*)sm;
        if (lane < 4)
#pragma unroll
            for (int nf = 0; nf < NF; nf++) {
                red[(wid * NF + nf) * 8 + tc * 2 + 0] = s0[nf];
                red[(wid * NF + nf) * 8 + tc * 2 + 1] = s1[nf];
            }
        __syncthreads();
        if (tid < WN * NF * 8) {
            const int wn2 = tid / (NF * 8);
            const int rem = tid - wn2 * NF * 8;
            const int nf = rem >> 3, j = rem & 7;
            float t = 0.f;
#pragma unroll
            for (int w2 = 0; w2 < WM; w2++)
                t += red[((wn2 * WM + w2) * NF + nf) * 8 + j];
            const int n = n0 + wn2 * (COUT / WN) + nf * 8 + j;
            part[((size_t)b * 8 + blockIdx.x) * 128 + n] = t;
        }
    } else {
#pragma unroll
        for (int mf = 0; mf < MF; mf++)
#pragma unroll
            for (int half = 0; half < 2; half++) {
                const int m  = M0 + mf * 16 + g + half * 8;
                const int px = px0 + m;
                const int oy = px >> LOGH, ox = px & (HOUT - 1);
                const size_t base =
                    (((size_t)b * OP + oy + 1) * OP + ox + 1) * NTOT + n0;
#pragma unroll
                for (int nf = 0; nf < NF; nf++) {
                    const int n = N0 + nf * 8 + tc * 2;
                    const float y0 = fmaxf(acc[mf][nf][half * 2 + 0] + __ldg(bias_g + n), 0.f);
                    const float y1 = fmaxf(acc[mf][nf][half * 2 + 1] + __ldg(bias_g + n + 1), 0.f);
                    const __nv_bfloat16 h0 = __float2bfloat16_rn(y0);
                    const __nv_bfloat16 h1 = __float2bfloat16_rn(y1);
                    const __nv_bfloat16 l0 = __float2bfloat16_rn(y0 - __bfloat162float(h0));
                    const __nv_bfloat16 l1 = __float2bfloat16_rn(y1 - __bfloat162float(h1));
                    *(u32*)(out_h + base + n) =
                        (u32)__bfloat16_as_ushort(h0) | ((u32)__bfloat16_as_ushort(h1) << 16);
                    *(u32*)(out_l + base + n) =
                        (u32)__bfloat16_as_ushort(l0) | ((u32)__bfloat16_as_ushort(l1) << 16);
                }
            }
    }
}

// ---------------------------------------------------------------------------
__global__ void __launch_bounds__(128) fc_k(const float* __restrict__ part,
                                            const float* __restrict__ fw,
                                            const float* __restrict__ fb,
                                            const int* __restrict__ region,
                                            float* __restrict__ out)
{
    __shared__ float f[128];
    const int b = blockIdx.x, tid = threadIdx.x;
    const int r = region[b] & (R_ - 1);
    float s = 0.0f;
#pragma unroll
    for (int q = 0; q < 8; q++) s += part[(b * 8 + q) * 128 + tid];
    f[tid] = s * (1.0f / 1024.0f);
    __syncthreads();
    if (tid < 32) {
        const float* w0 = fw + ((size_t)r * 2 + 0) * 128;
        const float* w1 = fw + ((size_t)r * 2 + 1) * 128;
        float p0 = 0.0f, p1 = 0.0f;
#pragma unroll
        for (int i = tid; i < 128; i += 32) {
            p0 = fmaf(f[i], w0[i], p0);
            p1 = fmaf(f[i], w1[i], p1);
        }
#pragma unroll
        for (int o = 16; o > 0; o >>= 1) {
            p0 += __shfl_down_sync(0xFFFFFFFFu, p0, o);
            p1 += __shfl_down_sync(0xFFFFFFFFu, p1, o);
        }
        if (tid == 0) {
            out[b * 2 + 0] = p0 + fb[r * 2 + 0];
            out[b * 2 + 1] = p1 + fb[r * 2 + 1];
        }
    }
}

// ---------------------------------------------------------------------------
extern "C" void kernel_launch(void* const* d_in, const int* in_sizes, int n_in,
                              void* d_out, int out_size)
{
    const float* image  = (const float*)d_in[0];
    const int*   region = (const int*)d_in[1];
    const float* w1     = (const float*)d_in[2];
    const float* b1     = (const float*)d_in[3];
    const float* w2     = (const float*)d_in[4];
    const float* b2     = (const float*)d_in[5];
    const float* w3     = (const float*)d_in[6];
    const float* b3     = (const float*)d_in[7];
    const float* fw     = (const float*)d_in[8];
    const float* fb     = (const float*)d_in[9];
    float* out = (float*)d_out;

    __nv_bfloat16 *imgh, *imgl, *b1h, *b1l, *b2h, *b2l, *w1img, *w2img, *w3img;
    float *part;
    cudaGetSymbolAddress((void**)&imgh, g_imgh);
    cudaGetSymbolAddress((void**)&imgl, g_imgl);
    cudaGetSymbolAddress((void**)&b1h, g_b1h);
    cudaGetSymbolAddress((void**)&b1l, g_b1l);
    cudaGetSymbolAddress((void**)&b2h, g_b2h);
    cudaGetSymbolAddress((void**)&b2l, g_b2l);
    cudaGetSymbolAddress((void**)&part, g_part);
    cudaGetSymbolAddress((void**)&w1img, g_w1img);
    cudaGetSymbolAddress((void**)&w2img, g_w2img);
    cudaGetSymbolAddress((void**)&w3img, g_w3img);

    prep_all<<<NB_IMG + NB_W1 + NB_W2 + NB_W3, 256>>>(
        image, imgh, imgl, w1, w1img, w2, w2img, w3, w3img);

    const int SM1 = 2 * 18720 + 2 * 32 * 144;     //  46656
    const int SM2 = 2 * (36864 + 2 * 64 * 144);   // 110592 -> 2 CTAs/SM
    const int SM3 = SM2;
    cudaFuncSetAttribute(conv1_k,
                         cudaFuncAttributeMaxDynamicSharedMemorySize, SM1);
    cudaFuncSetAttribute(conv_mma8<32, 5, 64, 64, 64, 6, 4, 2, false>,
                         cudaFuncAttributeMaxDynamicSharedMemorySize, SM2);
    cudaFuncSetAttribute(conv_mma8<64, 6, 64, 128, 32, 5, 4, 2, true>,
                         cudaFuncAttributeMaxDynamicSharedMemorySize, SM3);

    // conv1: direct-from-tile on padded image
    conv1_k<<<dim3(32, 1, B_), 256, SM1>>>(
        imgh, imgl, w1img, b1, region, b1h, b1l);
    // conv2: padded in/out
    conv_mma8<32, 5, 64, 64, 64, 6, 4, 2, false><<<dim3(32, 1, B_), 256, SM2>>>(
        b1h, b1l, w2img, b2, region, nullptr, b2h, b2l);
    // conv3: padded in, N-split + fused GAP
    conv_mma8<64, 6, 64, 128, 32, 5, 4, 2, true><<<dim3(8, 2, B_), 256, SM3>>>(
        b2h, b2l, w3img, b3, region, part, nullptr, nullptr);

    fc_k<<<B_, 128>>>(part, fw, fb, region, out);
}